// round 8
// baseline (speedup 1.0000x reference)
#include <cuda_runtime.h>
#include <cstdint>

// Problem constants (from reference)
#define B_SIZE 8192
#define K_SLOTS 32
#define D_OUT 1024
#define NUM_FEATURES 40960
#define PHASE_COLS 512          // columns per phase (2 phases)
#define THREADS 128             // 128 threads x float4 = 512 cols

// One CTA per (batch row, phase column-slice). Sequential launches per phase keep
// the active 80MB weight slice resident in L2 (126MB). Unroll-8 gather batches
// give 8 outstanding LDG.128 per thread to cover L2-hit latency.
__global__ __launch_bounds__(THREADS, 8)
void feature_transformer_phase_kernel(const int* __restrict__ feature_indices,   // [B,K] int32
                                      const float* __restrict__ feature_values,  // [B,K]
                                      const float* __restrict__ weight,          // [F,D]
                                      const float* __restrict__ bias,            // [D]
                                      float* __restrict__ out,                   // [B,D]
                                      int col_offset)
{
    const int b = blockIdx.x;
    const int tid = threadIdx.x;

    __shared__ int   s_idx[K_SLOTS];
    __shared__ float s_val[K_SLOTS];
    __shared__ int   s_count;

    // Warp 0: load (idx, val), compact out padded (-1) slots via ballot.
    if (tid < 32) {
        int   id = feature_indices[(size_t)b * K_SLOTS + tid];
        float v  = feature_values[(size_t)b * K_SLOTS + tid];
        bool valid = (id >= 0);
        unsigned mask = __ballot_sync(0xffffffffu, valid);
        int pos = __popc(mask & ((1u << tid) - 1u));
        if (valid) {
            s_idx[pos] = min(id, NUM_FEATURES - 1);   // mirror reference clip
            s_val[pos] = v;
        }
        if (tid == 0) s_count = __popc(mask);
    }
    __syncthreads();

    const int count = s_count;
    const int d = col_offset + tid * 4;      // this thread's 4 output columns
    const float* wbase = weight + d;

    float4 acc = *reinterpret_cast<const float4*>(bias + d);

    int k = 0;
    // 8-deep independent gather batches: all 8 LDG.128 issue before the FMA
    // chain consumes them -> 8 outstanding loads per thread.
    #pragma unroll 1
    for (; k + 8 <= count; k += 8) {
        float4 w[8];
        #pragma unroll
        for (int j = 0; j < 8; ++j)
            w[j] = __ldg(reinterpret_cast<const float4*>(wbase + (size_t)s_idx[k + j] * D_OUT));
        #pragma unroll
        for (int j = 0; j < 8; ++j) {
            const float v = s_val[k + j];
            acc.x += v * w[j].x; acc.y += v * w[j].y;
            acc.z += v * w[j].z; acc.w += v * w[j].w;
        }
    }
    if (k + 4 <= count) {
        float4 w[4];
        #pragma unroll
        for (int j = 0; j < 4; ++j)
            w[j] = __ldg(reinterpret_cast<const float4*>(wbase + (size_t)s_idx[k + j] * D_OUT));
        #pragma unroll
        for (int j = 0; j < 4; ++j) {
            const float v = s_val[k + j];
            acc.x += v * w[j].x; acc.y += v * w[j].y;
            acc.z += v * w[j].z; acc.w += v * w[j].w;
        }
        k += 4;
    }
    for (; k < count; ++k) {
        const float4 w = __ldg(reinterpret_cast<const float4*>(wbase + (size_t)s_idx[k] * D_OUT));
        const float v = s_val[k];
        acc.x += v * w.x; acc.y += v * w.y; acc.z += v * w.z; acc.w += v * w.w;
    }

    *reinterpret_cast<float4*>(out + (size_t)b * D_OUT + d) = acc;
}

extern "C" void kernel_launch(void* const* d_in, const int* in_sizes, int n_in,
                              void* d_out, int out_size)
{
    const int*   feature_indices = (const int*)d_in[0];
    const float* feature_values  = (const float*)d_in[1];
    const float* weight          = (const float*)d_in[2];
    const float* bias            = (const float*)d_in[3];
    float*       out             = (float*)d_out;

    // Two sequential phases over disjoint column slices; stream ordering gives
    // temporal separation so each 80MB weight slice stays L2-resident.
    for (int phase = 0; phase < D_OUT / PHASE_COLS; ++phase) {
        feature_transformer_phase_kernel<<<B_SIZE, THREADS>>>(
            feature_indices, feature_values, weight, bias, out,
            phase * PHASE_COLS);
    }
}

// round 15
// speedup vs baseline: 1.1983x; 1.1983x over previous
#include <cuda_runtime.h>
#include <cstdint>

// Problem constants (from reference)
#define B_SIZE 8192
#define K_SLOTS 32
#define D_OUT 1024
#define NUM_FEATURES 40960
#define PHASE_COLS 512          // columns per phase (2 phases)
#define THREADS 128             // 128 threads x float4 = 512 cols

// Fused phasing: grid (B, 2). Linear CTA order dispatches all phase-0 CTAs
// (cols 0..511) before phase-1, keeping the live 80MB weight slice L2-resident,
// while phase-1 CTAs backfill SMs as phase-0 drains (no launch-boundary bubble).
// The kernel runs at the B300 LTS structural cap (~6300 B/cyc): gather bytes
// are the binding resource, so config = max occupancy, minimal regs (unroll-4).
__global__ __launch_bounds__(THREADS, 16)
void feature_transformer_fused_kernel(const int* __restrict__ feature_indices,   // [B,K] int32
                                      const float* __restrict__ feature_values,  // [B,K]
                                      const float* __restrict__ weight,          // [F,D]
                                      const float* __restrict__ bias,            // [D]
                                      float* __restrict__ out)                   // [B,D]
{
    const int b = blockIdx.x;
    const int col_offset = blockIdx.y * PHASE_COLS;
    const int tid = threadIdx.x;

    __shared__ int   s_idx[K_SLOTS];
    __shared__ float s_val[K_SLOTS];
    __shared__ int   s_count;

    // Warp 0: load (idx, val), compact out padded (-1) slots via ballot.
    if (tid < 32) {
        int   id = feature_indices[(size_t)b * K_SLOTS + tid];
        float v  = feature_values[(size_t)b * K_SLOTS + tid];
        bool valid = (id >= 0);
        unsigned mask = __ballot_sync(0xffffffffu, valid);
        int pos = __popc(mask & ((1u << tid) - 1u));
        if (valid) {
            s_idx[pos] = min(id, NUM_FEATURES - 1);   // mirror reference clip
            s_val[pos] = v;
        }
        if (tid == 0) s_count = __popc(mask);
    }
    __syncthreads();

    const int count = s_count;
    const int d = col_offset + tid * 4;      // this thread's 4 output columns
    const float* wbase = weight + d;

    float4 acc = *reinterpret_cast<const float4*>(bias + d);

    // Independent float4 gathers across k -> 4 outstanding LDG.128 per thread,
    // ~27 warps/SM at occ~86% keeps the LTS pipe full.
    int k = 0;
    #pragma unroll 1
    for (; k + 4 <= count; k += 4) {
        const float4 w0 = __ldg(reinterpret_cast<const float4*>(wbase + (size_t)s_idx[k + 0] * D_OUT));
        const float4 w1 = __ldg(reinterpret_cast<const float4*>(wbase + (size_t)s_idx[k + 1] * D_OUT));
        const float4 w2 = __ldg(reinterpret_cast<const float4*>(wbase + (size_t)s_idx[k + 2] * D_OUT));
        const float4 w3 = __ldg(reinterpret_cast<const float4*>(wbase + (size_t)s_idx[k + 3] * D_OUT));
        const float v0 = s_val[k + 0];
        const float v1 = s_val[k + 1];
        const float v2 = s_val[k + 2];
        const float v3 = s_val[k + 3];
        acc.x += v0 * w0.x; acc.y += v0 * w0.y; acc.z += v0 * w0.z; acc.w += v0 * w0.w;
        acc.x += v1 * w1.x; acc.y += v1 * w1.y; acc.z += v1 * w1.z; acc.w += v1 * w1.w;
        acc.x += v2 * w2.x; acc.y += v2 * w2.y; acc.z += v2 * w2.z; acc.w += v2 * w2.w;
        acc.x += v3 * w3.x; acc.y += v3 * w3.y; acc.z += v3 * w3.z; acc.w += v3 * w3.w;
    }
    for (; k < count; ++k) {
        const float4 w = __ldg(reinterpret_cast<const float4*>(wbase + (size_t)s_idx[k] * D_OUT));
        const float v = s_val[k];
        acc.x += v * w.x; acc.y += v * w.y; acc.z += v * w.z; acc.w += v * w.w;
    }

    // Evict-first store: don't let 16MB/phase of output displace the
    // L2-resident weight slice.
    __stcs(reinterpret_cast<float4*>(out + (size_t)b * D_OUT + d), acc);
}

extern "C" void kernel_launch(void* const* d_in, const int* in_sizes, int n_in,
                              void* d_out, int out_size)
{
    const int*   feature_indices = (const int*)d_in[0];
    const float* feature_values  = (const float*)d_in[1];
    const float* weight          = (const float*)d_in[2];
    const float* bias            = (const float*)d_in[3];
    float*       out             = (float*)d_out;

    dim3 grid(B_SIZE, D_OUT / PHASE_COLS);
    feature_transformer_fused_kernel<<<grid, THREADS>>>(feature_indices, feature_values,
                                                        weight, bias, out);
}